// round 16
// baseline (speedup 1.0000x reference)
#include <cuda_runtime.h>
#include <cuda_fp16.h>
#include <cstdint>
#include <math.h>

// ---------------- constants ----------------
#define DM 2048
#define NH 16
#define HD 128
#define LORA 512
#define SEQ 2048
#define BATCH 2
#define ROWS (BATCH*SEQ)   // 4096

// ---------------- scratch (fp16 operands, fp32 accum everywhere) ----------------
__device__ __half g_kvlat[ROWS * LORA];
__device__ __half g_k[ROWS * DM];
__device__ __half g_v[ROWS * DM];
__device__ __half g_q[ROWS * DM];
__device__ __half g_attn[ROWS * DM];
__device__ __half g_wkvcT[LORA * DM];
__device__ __half g_wkT[DM * LORA];
__device__ __half g_wvT[DM * LORA];
__device__ __half g_wqT[DM * DM];
__device__ __half g_woT[DM * DM];

// ---------------- helpers ----------------
__device__ __forceinline__ uint32_t smem_addr(const void* p) {
    return (uint32_t)__cvta_generic_to_shared(p);
}
__device__ __forceinline__ void cpasync16(uint32_t s, const void* g) {
    asm volatile("cp.async.cg.shared.global [%0], [%1], 16;" :: "r"(s), "l"(g));
}
#define CP_COMMIT asm volatile("cp.async.commit_group;" ::: "memory")
#define CP_WAIT0  asm volatile("cp.async.wait_group 0;" ::: "memory")
#define CP_WAIT1  asm volatile("cp.async.wait_group 1;" ::: "memory")

// mma.sync m16n8k16 fp16 in, fp32 accum: D += A@B ; A row-major, B col-major
__device__ __forceinline__ void mma16(float* c, const uint32_t* a, const uint32_t* b) {
    asm volatile(
        "mma.sync.aligned.m16n8k16.row.col.f32.f16.f16.f32 "
        "{%0,%1,%2,%3}, {%4,%5,%6,%7}, {%8,%9}, {%0,%1,%2,%3};"
        : "+f"(c[0]), "+f"(c[1]), "+f"(c[2]), "+f"(c[3])
        : "r"(a[0]), "r"(a[1]), "r"(a[2]), "r"(a[3]), "r"(b[0]), "r"(b[1]));
}
__device__ __forceinline__ void ldsm4(uint32_t* r, uint32_t addr) {
    asm volatile("ldmatrix.sync.aligned.m8n8.x4.shared.b16 {%0,%1,%2,%3}, [%4];"
        : "=r"(r[0]), "=r"(r[1]), "=r"(r[2]), "=r"(r[3]) : "r"(addr));
}
__device__ __forceinline__ void ldsm4t(uint32_t* r, uint32_t addr) {
    asm volatile("ldmatrix.sync.aligned.m8n8.x4.trans.shared.b16 {%0,%1,%2,%3}, [%4];"
        : "=r"(r[0]), "=r"(r[1]), "=r"(r[2]), "=r"(r[3]) : "r"(addr));
}
__device__ __forceinline__ uint32_t packh2(float lo, float hi) {
    __half2 h = __floats2half2_rn(lo, hi);
    return *(uint32_t*)&h;
}

// ================= fp16 mma.sync GEMM =================
// C[M,N] = A[M,K] @ Bt[N,K]^T ; CTA 128x128, BK=64, 8 warps (warp 64x32).
// 2-stage pipeline, 72KB smem -> 2 CTAs/SM.
// AT=float: A is fp32 in gmem, converted (rn) to fp16 during the smem store.
// Runtime fused-RoPE epilogue (fc != nullptr, primary only) and optional
// second (Bt2, C2, N2) problem sharing the same A: blocks with
// blockIdx.x >= nsplit compute C2[M,N2] = A @ Bt2^T (no rope).
#define GSTAGES 2
#define GSTRH 72                       // halfs per row (64 + 8 pad)
#define GSTAGE_H (128*GSTRH*2)         // A + B halfs per stage
#define GEMM_SMEM (GSTAGES*GSTAGE_H*2) // 73728 B

template<typename CT, typename AT>
__global__ __launch_bounds__(256, 2)
void gemm_f16(const AT* __restrict__ A, const __half* __restrict__ Bt0,
              CT* __restrict__ C0, int M, int N, int K,
              const float* __restrict__ fc, const float* __restrict__ fs,
              const __half* __restrict__ Bt2, CT* __restrict__ C2,
              int nsplit, int N2)
{
    extern __shared__ __half smh[];
    const int tid = threadIdx.x, wid = tid >> 5, lane = tid & 31;
    const int g = lane >> 2, tg = lane & 3;
    const int wm = wid >> 2, wn = wid & 3;     // 2 x 4 warp grid, warp = 64x32
    int bx = blockIdx.x;
    const __half* Bt = Bt0;
    CT* C = C0;
    int Nc = N;
    bool rope = (fc != nullptr);
    if (Bt2 != nullptr && bx >= nsplit) { Bt = Bt2; C = C2; bx -= nsplit; rope = false; Nc = N2; }
    const int m0 = blockIdx.y * 128, n0 = bx * 128;
    const int NC = K >> 6;
    const int lrA = lane & 15, lcA = (lane >> 4) << 3;
    const int lrB4 = (lane & 7) | ((lane >> 4) << 3);
    const int lcB4 = ((lane >> 3) & 1) << 3;

    float c[4][4][4];
#pragma unroll
    for (int mt = 0; mt < 4; mt++)
#pragma unroll
        for (int nt = 0; nt < 4; nt++)
#pragma unroll
            for (int j = 0; j < 4; j++) c[mt][nt][j] = 0.f;

    auto load_chunk = [&](int stage, int ch) {
        __half* As = smh + stage * GSTAGE_H;
        __half* Bs = As + 128 * GSTRH;
        const AT* Ag = A + (size_t)m0 * K + ch * 64;
        const __half* Bg = Bt + (size_t)n0 * K + ch * 64;
        if constexpr (sizeof(AT) == 2) {
            // fp16 A: cp.async, 1024 granules of 8 halfs
#pragma unroll
            for (int i = 0; i < 4; i++) {
                int idx = tid + i * 256;
                int row = idx >> 3, gc = (idx & 7) << 3;
                cpasync16(smem_addr(As + row * GSTRH + gc), Ag + (size_t)row * K + gc);
            }
        } else {
            // fp32 A: LDG.128 + rn-convert + STS (2048 granules of 4 floats)
#pragma unroll
            for (int i = 0; i < 8; i += 2) {
                int idx0 = tid + i * 256;
                int idx1 = tid + (i + 1) * 256;
                int r0 = idx0 >> 4, c0 = (idx0 & 15) << 2;
                int r1 = idx1 >> 4, c1 = (idx1 & 15) << 2;
                float4 v0 = *(const float4*)(Ag + (size_t)r0 * K + c0);
                float4 v1 = *(const float4*)(Ag + (size_t)r1 * K + c1);
                uint2 h0 = make_uint2(packh2(v0.x, v0.y), packh2(v0.z, v0.w));
                uint2 h1 = make_uint2(packh2(v1.x, v1.y), packh2(v1.z, v1.w));
                *(uint2*)(As + r0 * GSTRH + c0) = h0;
                *(uint2*)(As + r1 * GSTRH + c1) = h1;
            }
        }
#pragma unroll
        for (int i = 0; i < 4; i++) {
            int idx = tid + i * 256;
            int row = idx >> 3, gc = (idx & 7) << 3;
            cpasync16(smem_addr(Bs + row * GSTRH + gc), Bg + (size_t)row * K + gc);
        }
    };

    load_chunk(0, 0);
    CP_COMMIT;

    for (int ch = 0; ch < NC; ch++) {
        int pf = ch + 1;
        if (pf < NC) { load_chunk(pf & 1, pf); CP_COMMIT; CP_WAIT1; }
        else         { CP_WAIT0; }
        __syncthreads();

        const __half* As = smh + (ch & 1) * GSTAGE_H;
        const __half* Bs = As + 128 * GSTRH;
#pragma unroll
        for (int ks = 0; ks < 4; ks++) {
            const int kk = ks * 16;
            uint32_t a[4][4], b[2][4];
#pragma unroll
            for (int mt = 0; mt < 4; mt++)
                ldsm4(a[mt], smem_addr(As + (wm * 64 + mt * 16 + lrA) * GSTRH + kk + lcA));
#pragma unroll
            for (int nt2 = 0; nt2 < 2; nt2++)
                ldsm4(b[nt2], smem_addr(Bs + (wn * 32 + nt2 * 16 + lrB4) * GSTRH + kk + lcB4));
#pragma unroll
            for (int mt = 0; mt < 4; mt++)
#pragma unroll
                for (int nt2 = 0; nt2 < 2; nt2++) {
                    mma16(c[mt][nt2 * 2 + 0], a[mt], b[nt2] + 0);
                    mma16(c[mt][nt2 * 2 + 1], a[mt], b[nt2] + 2);
                }
        }
        __syncthreads();   // all reads of this stage done before it is refilled
    }

    // epilogue (+ optional fused RoPE on fp32 accumulators)
#pragma unroll
    for (int mt = 0; mt < 4; mt++) {
        int row = m0 + wm * 64 + mt * 16 + g;
#pragma unroll
        for (int nt = 0; nt < 4; nt++) {
            int col = n0 + wn * 32 + nt * 8 + 2 * tg;
            float v0 = c[mt][nt][0], v1 = c[mt][nt][1];
            float v2 = c[mt][nt][2], v3 = c[mt][nt][3];
            if (rope) {
                int p = (col & 127) >> 1;
                int s0 = row & (SEQ - 1);
                int s1 = (row + 8) & (SEQ - 1);
                float c0 = fc[s0 * 64 + p], n0v = fs[s0 * 64 + p];
                float c1 = fc[s1 * 64 + p], n1v = fs[s1 * 64 + p];
                float t0 = v0 * c0 - v1 * n0v, t1 = v0 * n0v + v1 * c0;
                float t2 = v2 * c1 - v3 * n1v, t3 = v2 * n1v + v3 * c1;
                v0 = t0; v1 = t1; v2 = t2; v3 = t3;
            }
            if constexpr (sizeof(CT) == 2) {
                *(__half2*)&C[(size_t)row * Nc + col] = __floats2half2_rn(v0, v1);
                *(__half2*)&C[(size_t)(row + 8) * Nc + col] = __floats2half2_rn(v2, v3);
            } else {
                *(float2*)&C[(size_t)row * Nc + col] = make_float2(v0, v1);
                *(float2*)&C[(size_t)(row + 8) * Nc + col] = make_float2(v2, v3);
            }
        }
    }
}

// ================= flash attention (causal), fp16 mma.sync =================
// BM=128 q, BN=128 kv. 8 warps, each owns 16 q rows x full 128 kv. P in regs.
// K and V in natural [seq][hd] layout (V B-frags via ldmatrix.trans).
// K/V tiles double-buffered (170KB smem); Q loaded once. One batch per launch.
#define QSTRH 136                       // 128 + 8 pad
#define FQ_H (128*QSTRH)
#define FKV_H (128*QSTRH)
#define FLASH_SMEM ((FQ_H + 4*FKV_H) * 2)   // 174080 B

__global__ __launch_bounds__(256, 1)
void flash_f16(const __half* __restrict__ Q, const __half* __restrict__ K,
               const __half* __restrict__ V, __half* __restrict__ O, int b)
{
    extern __shared__ __half smh[];
    __half* Qs = smh;
    __half* Ks = Qs + FQ_H;              // 2 buffers
    __half* Vs = Ks + 2 * FKV_H;         // 2 buffers

    const int tid = threadIdx.x, wid = tid >> 5, lane = tid & 31;
    const int g = lane >> 2, tg = lane & 3;
    const int qt = (int)(gridDim.x - 1) - (int)blockIdx.x;   // heavy tiles first
    const int h = blockIdx.y;
    const int row0 = b * SEQ + qt * 128;
    const float scale = 0.08838834764831845f;
    const int lrA = lane & 15, lcA = (lane >> 4) << 3;
    const int lrB4 = (lane & 7) | ((lane >> 4) << 3);
    const int lcB4 = ((lane >> 3) & 1) << 3;
    const int lrV = (lane & 7) | ((lane >> 3) & 1) << 3;
    const int lcV = (lane >> 4) << 3;

    auto issue_tile = [&](int jt) {
        const int kv0 = jt << 7;
        __half* Kb = Ks + (jt & 1) * FKV_H;
        __half* Vb = Vs + (jt & 1) * FKV_H;
#pragma unroll
        for (int i = 0; i < 8; i++) {           // K: 128 rows x 16 granules
            int idx = tid + i * 256;
            int row = idx >> 4, gc = (idx & 15) << 3;
            cpasync16(smem_addr(Kb + row * QSTRH + gc),
                      K + (size_t)(b * SEQ + kv0 + row) * DM + h * HD + gc);
        }
#pragma unroll
        for (int i = 0; i < 8; i++) {           // V: same natural layout
            int idx = tid + i * 256;
            int row = idx >> 4, gc = (idx & 15) << 3;
            cpasync16(smem_addr(Vb + row * QSTRH + gc),
                      V + (size_t)(b * SEQ + kv0 + row) * DM + h * HD + gc);
        }
    };

    // Q tile: 128 rows x 16 granules = 2048
#pragma unroll
    for (int i = 0; i < 8; i++) {
        int idx = tid + i * 256;
        int row = idx >> 4, gc = (idx & 15) << 3;
        cpasync16(smem_addr(Qs + row * QSTRH + gc),
                  Q + (size_t)(row0 + row) * DM + h * HD + gc);
    }
    CP_COMMIT;
    issue_tile(0);
    CP_COMMIT;

    float o[16][4];
#pragma unroll
    for (int nt = 0; nt < 16; nt++)
#pragma unroll
        for (int j = 0; j < 4; j++) o[nt][j] = 0.f;
    float mrun0 = -INFINITY, mrun1 = -INFINITY, l0 = 0.f, l1 = 0.f;

    const int ntiles = qt + 1;
    const int qr0 = qt * 128 + wid * 16 + g;
    const int qr1 = qr0 + 8;

    for (int jt = 0; jt < ntiles; jt++) {
        const int kv0 = jt << 7;
        __syncthreads();                       // all warps done with buffer being refilled
        bool pf = (jt + 1 < ntiles);
        if (pf) issue_tile(jt + 1);
        CP_COMMIT;
        if (pf) { CP_WAIT1; } else { CP_WAIT0; }
        __syncthreads();

        const __half* Kb = Ks + (jt & 1) * FKV_H;
        const __half* Vb = Vs + (jt & 1) * FKV_H;

        // ---- S = Q @ K^T : this warp's 16 q rows x 128 kv
        float sc[16][4];
#pragma unroll
        for (int nt = 0; nt < 16; nt++)
#pragma unroll
            for (int j = 0; j < 4; j++) sc[nt][j] = 0.f;

#pragma unroll
        for (int ks = 0; ks < 8; ks++) {
            const int kk = ks * 16;
            uint32_t a[4];
            ldsm4(a, smem_addr(Qs + (wid * 16 + lrA) * QSTRH + kk + lcA));
#pragma unroll
            for (int nt2 = 0; nt2 < 8; nt2++) {
                uint32_t bf[4];
                ldsm4(bf, smem_addr(Kb + (nt2 * 16 + lrB4) * QSTRH + kk + lcB4));
                mma16(sc[nt2 * 2 + 0], a, bf + 0);
                mma16(sc[nt2 * 2 + 1], a, bf + 2);
            }
        }

        // ---- scale + causal mask (only the diagonal tile needs masking)
        const bool need_mask = (jt == qt);
#pragma unroll
        for (int nt = 0; nt < 16; nt++) {
            int kc = kv0 + nt * 8 + 2 * tg;
#pragma unroll
            for (int j = 0; j < 4; j++) {
                float s = sc[nt][j] * scale;
                if (need_mask) {
                    int qr = (j >= 2) ? qr1 : qr0;
                    if (kc + (j & 1) > qr) s = -1e30f;
                }
                sc[nt][j] = s;
            }
        }

        // ---- in-warp online softmax (rows g and g+8 of this warp's block)
        float mx0 = -INFINITY, mx1 = -INFINITY;
#pragma unroll
        for (int nt = 0; nt < 16; nt++) {
            mx0 = fmaxf(mx0, fmaxf(sc[nt][0], sc[nt][1]));
            mx1 = fmaxf(mx1, fmaxf(sc[nt][2], sc[nt][3]));
        }
        mx0 = fmaxf(mx0, __shfl_xor_sync(0xffffffffu, mx0, 1));
        mx0 = fmaxf(mx0, __shfl_xor_sync(0xffffffffu, mx0, 2));
        mx1 = fmaxf(mx1, __shfl_xor_sync(0xffffffffu, mx1, 1));
        mx1 = fmaxf(mx1, __shfl_xor_sync(0xffffffffu, mx1, 2));
        float mn0 = fmaxf(mrun0, mx0), mn1 = fmaxf(mrun1, mx1);
        float fac0 = __expf(mrun0 - mn0), fac1 = __expf(mrun1 - mn1);
        mrun0 = mn0; mrun1 = mn1;

        float s0 = 0.f, s1 = 0.f;
#pragma unroll
        for (int nt = 0; nt < 16; nt++) {
            sc[nt][0] = __expf(sc[nt][0] - mn0);
            sc[nt][1] = __expf(sc[nt][1] - mn0);
            sc[nt][2] = __expf(sc[nt][2] - mn1);
            sc[nt][3] = __expf(sc[nt][3] - mn1);
            s0 += sc[nt][0] + sc[nt][1];
            s1 += sc[nt][2] + sc[nt][3];
        }
        s0 += __shfl_xor_sync(0xffffffffu, s0, 1);
        s0 += __shfl_xor_sync(0xffffffffu, s0, 2);
        s1 += __shfl_xor_sync(0xffffffffu, s1, 1);
        s1 += __shfl_xor_sync(0xffffffffu, s1, 2);
        l0 = l0 * fac0 + s0;
        l1 = l1 * fac1 + s1;

#pragma unroll
        for (int nt = 0; nt < 16; nt++) {
            o[nt][0] *= fac0; o[nt][1] *= fac0;
            o[nt][2] *= fac1; o[nt][3] *= fac1;
        }

        // ---- O += P @ V ; P packed from sc regs; V B-frags via ldmatrix.trans
#pragma unroll
        for (int kb = 0; kb < 8; kb++) {
            uint32_t a[4];
            a[0] = packh2(sc[2 * kb][0],     sc[2 * kb][1]);
            a[1] = packh2(sc[2 * kb][2],     sc[2 * kb][3]);
            a[2] = packh2(sc[2 * kb + 1][0], sc[2 * kb + 1][1]);
            a[3] = packh2(sc[2 * kb + 1][2], sc[2 * kb + 1][3]);
            const int kk = kb * 16;
#pragma unroll
            for (int nt2 = 0; nt2 < 8; nt2++) {
                uint32_t bf[4];
                ldsm4t(bf, smem_addr(Vb + (kk + lrV) * QSTRH + nt2 * 16 + lcV));
                mma16(o[nt2 * 2 + 0], a, bf + 0);
                mma16(o[nt2 * 2 + 1], a, bf + 2);
            }
        }
    }

    // ---- epilogue
    float inv0 = 1.0f / l0, inv1 = 1.0f / l1;
    int row = row0 + wid * 16 + g;
#pragma unroll
    for (int nt = 0; nt < 16; nt++) {
        int col = h * HD + nt * 8 + 2 * tg;
        *(__half2*)&O[(size_t)row * DM + col] =
            __floats2half2_rn(o[nt][0] * inv0, o[nt][1] * inv0);
        *(__half2*)&O[(size_t)(row + 8) * DM + col] =
            __floats2half2_rn(o[nt][2] * inv1, o[nt][3] * inv1);
    }
}

// ---------------- small kernels ----------------
// src float: transpose [r,c] -> dst half [c,r]
__global__ __launch_bounds__(256) void trans_cvt(const float* __restrict__ src,
                                                 __half* __restrict__ dst, int R, int C)
{
    __shared__ float t[32][33];
    int c0 = blockIdx.x * 32, r0 = blockIdx.y * 32;
    int tx = threadIdx.x & 31, ty = threadIdx.x >> 5;
#pragma unroll
    for (int i = 0; i < 4; i++)
        t[ty + i * 8][tx] = src[(size_t)(r0 + ty + i * 8) * C + c0 + tx];
    __syncthreads();
#pragma unroll
    for (int i = 0; i < 4; i++)
        dst[(size_t)(c0 + ty + i * 8) * R + r0 + tx] = __float2half_rn(t[tx][ty + i * 8]);
}

__global__ __launch_bounds__(256) void rmsnorm_kernel(__half* __restrict__ x,
                                                      const float* __restrict__ w)
{
    const int row = blockIdx.x;
    __half* p = x + (size_t)row * LORA;
    const int t = threadIdx.x;
    float v0 = __half2float(p[t]), v1 = __half2float(p[t + 256]);
    float ss = v0 * v0 + v1 * v1;
#pragma unroll
    for (int o = 16; o; o >>= 1) ss += __shfl_xor_sync(0xffffffffu, ss, o);
    __shared__ float sred[8];
    if ((t & 31) == 0) sred[t >> 5] = ss;
    __syncthreads();
    float tot = 0.f;
#pragma unroll
    for (int i = 0; i < 8; i++) tot += sred[i];
    float inv = rsqrtf(tot * (1.0f / (float)LORA) + 1e-6f);
    p[t]       = __float2half_rn(v0 * inv * w[t]);
    p[t + 256] = __float2half_rn(v1 * inv * w[t + 256]);
}

// ---------------- launch ----------------
extern "C" void kernel_launch(void* const* d_in, const int* in_sizes, int n_in,
                              void* d_out, int out_size)
{
    const float* x     = (const float*)d_in[0];
    const float* fcos  = (const float*)d_in[1];
    const float* fsin  = (const float*)d_in[2];
    const float* w_kvc = (const float*)d_in[3];
    const float* kvw   = (const float*)d_in[4];
    const float* w_k   = (const float*)d_in[5];
    const float* w_v   = (const float*)d_in[6];
    const float* w_q   = (const float*)d_in[7];
    const float* w_o   = (const float*)d_in[8];
    float* out = (float*)d_out;

    __half *kvl, *Kb, *Vb, *Qb, *Ab;
    __half *wkvcT, *wkT, *wvT, *wqT, *woT;
    cudaGetSymbolAddress((void**)&kvl, g_kvlat);
    cudaGetSymbolAddress((void**)&Kb, g_k);
    cudaGetSymbolAddress((void**)&Vb, g_v);
    cudaGetSymbolAddress((void**)&Qb, g_q);
    cudaGetSymbolAddress((void**)&Ab, g_attn);
    cudaGetSymbolAddress((void**)&wkvcT, g_wkvcT);
    cudaGetSymbolAddress((void**)&wkT, g_wkT);
    cudaGetSymbolAddress((void**)&wvT, g_wvT);
    cudaGetSymbolAddress((void**)&wqT, g_wqT);
    cudaGetSymbolAddress((void**)&woT, g_woT);

    cudaFuncSetAttribute((void*)gemm_f16<__half, float>,  cudaFuncAttributeMaxDynamicSharedMemorySize, GEMM_SMEM);
    cudaFuncSetAttribute((void*)gemm_f16<__half, __half>, cudaFuncAttributeMaxDynamicSharedMemorySize, GEMM_SMEM);
    cudaFuncSetAttribute((void*)gemm_f16<float, __half>,  cudaFuncAttributeMaxDynamicSharedMemorySize, GEMM_SMEM);
    cudaFuncSetAttribute((void*)flash_f16, cudaFuncAttributeMaxDynamicSharedMemorySize, FLASH_SMEM);

    // one-time side streams + events (host resources; identical GPU work every call)
    static cudaStream_t s2 = nullptr;
    static cudaEvent_t ev_root = nullptr, ev_w1 = nullptr, ev_w = nullptr,
                       ev_f0 = nullptr, ev_out0 = nullptr;
    if (s2 == nullptr) {
        cudaStreamCreateWithFlags(&s2, cudaStreamNonBlocking);
        cudaEventCreateWithFlags(&ev_root, cudaEventDisableTiming);
        cudaEventCreateWithFlags(&ev_w1, cudaEventDisableTiming);
        cudaEventCreateWithFlags(&ev_w, cudaEventDisableTiming);
        cudaEventCreateWithFlags(&ev_f0, cudaEventDisableTiming);
        cudaEventCreateWithFlags(&ev_out0, cudaEventDisableTiming);
    }

    // ---- fork: root event on the capturing (main) stream FIRST ----
    cudaEventRecord(ev_root, 0);
    cudaStreamWaitEvent(s2, ev_root, 0);

    // ---- main: wq transpose (needed first, largest) ----
    trans_cvt<<<dim3(DM / 32, DM / 32), 256>>>(w_q, wqT, DM, DM);
    // ---- s2: wkvc transpose in parallel, then remaining weights ----
    trans_cvt<<<dim3(LORA / 32, DM / 32), 256, 0, s2>>>(w_kvc, wkvcT, DM, LORA);
    cudaEventRecord(ev_w1, s2);
    trans_cvt<<<dim3(DM / 32, LORA / 32), 256, 0, s2>>>(w_k, wkT, LORA, DM);
    trans_cvt<<<dim3(DM / 32, LORA / 32), 256, 0, s2>>>(w_v, wvT, LORA, DM);
    trans_cvt<<<dim3(DM / 32, DM / 32), 256, 0, s2>>>(w_o, woT, DM, DM);
    cudaEventRecord(ev_w, s2);

    // ---- main: merged q (rope) + kvc GEMM, one 640-CTA launch, A = x fp32 ----
    cudaStreamWaitEvent(0, ev_w1, 0);
    gemm_f16<__half, float><<<dim3(DM / 128 + LORA / 128, ROWS / 128), 256, GEMM_SMEM>>>(
        x, wqT, Qb, ROWS, DM, DM, fcos, fsin, wkvcT, kvl, DM / 128, LORA);
    rmsnorm_kernel<<<ROWS, 256>>>(kvl, kvw);
    cudaStreamWaitEvent(0, ev_w, 0);
    // merged k-up (rope) + v-up (no rope): one 1024-CTA launch
    gemm_f16<__half, __half><<<dim3(2 * (DM / 128), ROWS / 128), 256, GEMM_SMEM>>>(
        kvl, wkT, Kb, ROWS, DM, LORA, fcos, fsin, wvT, Vb, DM / 128, DM);

    // ---- flash (batch-split) with out-GEMM overlap ----
    // flash batch 0
    flash_f16<<<dim3(SEQ / 128, NH, 1), 256, FLASH_SMEM>>>(Qb, Kb, Vb, Ab, 0);
    cudaEventRecord(ev_f0, 0);
    // flash batch 1 (main) overlaps out-GEMM of batch-0 rows (s2; woT ready in s2 order)
    flash_f16<<<dim3(SEQ / 128, NH, 1), 256, FLASH_SMEM>>>(Qb, Kb, Vb, Ab, 1);
    cudaStreamWaitEvent(s2, ev_f0, 0);
    gemm_f16<float, __half><<<dim3(DM / 128, SEQ / 128), 256, GEMM_SMEM, s2>>>(
        Ab, woT, out, SEQ, DM, DM, nullptr, nullptr, nullptr, nullptr, 0, DM);
    cudaEventRecord(ev_out0, s2);
    // out-GEMM for batch-1 rows on main
    gemm_f16<float, __half><<<dim3(DM / 128, SEQ / 128), 256, GEMM_SMEM>>>(
        Ab + (size_t)SEQ * DM, woT, out + (size_t)SEQ * DM, SEQ, DM, DM,
        nullptr, nullptr, nullptr, nullptr, 0, DM);
    // join side stream back into main before capture ends
    cudaStreamWaitEvent(0, ev_out0, 0);
}

// round 17
// speedup vs baseline: 1.1077x; 1.1077x over previous
#include <cuda_runtime.h>
#include <cuda_fp16.h>
#include <cstdint>
#include <math.h>

// ---------------- constants ----------------
#define DM 2048
#define NH 16
#define HD 128
#define LORA 512
#define SEQ 2048
#define BATCH 2
#define ROWS (BATCH*SEQ)   // 4096

// ---------------- scratch (fp16 operands, fp32 accum everywhere) ----------------
__device__ __half g_kvlat[ROWS * LORA];
__device__ __half g_k[ROWS * DM];
__device__ __half g_v[ROWS * DM];
__device__ __half g_q[ROWS * DM];
__device__ __half g_attn[ROWS * DM];
__device__ __half g_wkvcT[LORA * DM];
__device__ __half g_wkT[DM * LORA];
__device__ __half g_wvT[DM * LORA];
__device__ __half g_wqT[DM * DM];
__device__ __half g_woT[DM * DM];

// ---------------- helpers ----------------
__device__ __forceinline__ uint32_t smem_addr(const void* p) {
    return (uint32_t)__cvta_generic_to_shared(p);
}
__device__ __forceinline__ void cpasync16(uint32_t s, const void* g) {
    asm volatile("cp.async.cg.shared.global [%0], [%1], 16;" :: "r"(s), "l"(g));
}
#define CP_COMMIT asm volatile("cp.async.commit_group;" ::: "memory")
#define CP_WAIT0  asm volatile("cp.async.wait_group 0;" ::: "memory")
#define CP_WAIT1  asm volatile("cp.async.wait_group 1;" ::: "memory")

// mma.sync m16n8k16 fp16 in, fp32 accum: D += A@B ; A row-major, B col-major
__device__ __forceinline__ void mma16(float* c, const uint32_t* a, const uint32_t* b) {
    asm volatile(
        "mma.sync.aligned.m16n8k16.row.col.f32.f16.f16.f32 "
        "{%0,%1,%2,%3}, {%4,%5,%6,%7}, {%8,%9}, {%0,%1,%2,%3};"
        : "+f"(c[0]), "+f"(c[1]), "+f"(c[2]), "+f"(c[3])
        : "r"(a[0]), "r"(a[1]), "r"(a[2]), "r"(a[3]), "r"(b[0]), "r"(b[1]));
}
__device__ __forceinline__ void ldsm4(uint32_t* r, uint32_t addr) {
    asm volatile("ldmatrix.sync.aligned.m8n8.x4.shared.b16 {%0,%1,%2,%3}, [%4];"
        : "=r"(r[0]), "=r"(r[1]), "=r"(r[2]), "=r"(r[3]) : "r"(addr));
}
__device__ __forceinline__ void ldsm4t(uint32_t* r, uint32_t addr) {
    asm volatile("ldmatrix.sync.aligned.m8n8.x4.trans.shared.b16 {%0,%1,%2,%3}, [%4];"
        : "=r"(r[0]), "=r"(r[1]), "=r"(r[2]), "=r"(r[3]) : "r"(addr));
}
__device__ __forceinline__ uint32_t packh2(float lo, float hi) {
    __half2 h = __floats2half2_rn(lo, hi);
    return *(uint32_t*)&h;
}

// ================= fp16 mma.sync GEMM =================
// C[M,N] = A[M,K] @ Bt[N,K]^T ; CTA 128x128, BK=64, 8 warps (warp 64x32).
// 2-stage pipeline, 72KB smem -> 2 CTAs/SM.
// AT=float: A is fp32 in gmem, converted (rn) to fp16 during the smem store.
// Runtime fused-RoPE epilogue (fc != nullptr) and optional second (Bt2, C2)
// problem sharing the same A (k-up + v-up merge; same N).
#define GSTAGES 2
#define GSTRH 72                       // halfs per row (64 + 8 pad)
#define GSTAGE_H (128*GSTRH*2)         // A + B halfs per stage
#define GEMM_SMEM (GSTAGES*GSTAGE_H*2) // 73728 B

template<typename CT, typename AT>
__global__ __launch_bounds__(256, 2)
void gemm_f16(const AT* __restrict__ A, const __half* __restrict__ Bt0,
              CT* __restrict__ C0, int M, int N, int K,
              const float* __restrict__ fc, const float* __restrict__ fs,
              const __half* __restrict__ Bt2, CT* __restrict__ C2, int nsplit)
{
    extern __shared__ __half smh[];
    const int tid = threadIdx.x, wid = tid >> 5, lane = tid & 31;
    const int g = lane >> 2, tg = lane & 3;
    const int wm = wid >> 2, wn = wid & 3;     // 2 x 4 warp grid, warp = 64x32
    int bx = blockIdx.x;
    const __half* Bt = Bt0;
    CT* C = C0;
    bool rope = (fc != nullptr);
    if (Bt2 != nullptr && bx >= nsplit) { Bt = Bt2; C = C2; bx -= nsplit; rope = false; }
    const int m0 = blockIdx.y * 128, n0 = bx * 128;
    const int NC = K >> 6;
    const int lrA = lane & 15, lcA = (lane >> 4) << 3;
    const int lrB4 = (lane & 7) | ((lane >> 4) << 3);
    const int lcB4 = ((lane >> 3) & 1) << 3;

    float c[4][4][4];
#pragma unroll
    for (int mt = 0; mt < 4; mt++)
#pragma unroll
        for (int nt = 0; nt < 4; nt++)
#pragma unroll
            for (int j = 0; j < 4; j++) c[mt][nt][j] = 0.f;

    auto load_chunk = [&](int stage, int ch) {
        __half* As = smh + stage * GSTAGE_H;
        __half* Bs = As + 128 * GSTRH;
        const AT* Ag = A + (size_t)m0 * K + ch * 64;
        const __half* Bg = Bt + (size_t)n0 * K + ch * 64;
        if constexpr (sizeof(AT) == 2) {
            // fp16 A: cp.async, 1024 granules of 8 halfs
#pragma unroll
            for (int i = 0; i < 4; i++) {
                int idx = tid + i * 256;
                int row = idx >> 3, gc = (idx & 7) << 3;
                cpasync16(smem_addr(As + row * GSTRH + gc), Ag + (size_t)row * K + gc);
            }
        } else {
            // fp32 A: LDG.128 + rn-convert + STS (2048 granules of 4 floats)
#pragma unroll
            for (int i = 0; i < 8; i += 2) {
                int idx0 = tid + i * 256;
                int idx1 = tid + (i + 1) * 256;
                int r0 = idx0 >> 4, c0 = (idx0 & 15) << 2;
                int r1 = idx1 >> 4, c1 = (idx1 & 15) << 2;
                float4 v0 = *(const float4*)(Ag + (size_t)r0 * K + c0);
                float4 v1 = *(const float4*)(Ag + (size_t)r1 * K + c1);
                uint2 h0 = make_uint2(packh2(v0.x, v0.y), packh2(v0.z, v0.w));
                uint2 h1 = make_uint2(packh2(v1.x, v1.y), packh2(v1.z, v1.w));
                *(uint2*)(As + r0 * GSTRH + c0) = h0;
                *(uint2*)(As + r1 * GSTRH + c1) = h1;
            }
        }
#pragma unroll
        for (int i = 0; i < 4; i++) {
            int idx = tid + i * 256;
            int row = idx >> 3, gc = (idx & 7) << 3;
            cpasync16(smem_addr(Bs + row * GSTRH + gc), Bg + (size_t)row * K + gc);
        }
    };

    load_chunk(0, 0);
    CP_COMMIT;

    for (int ch = 0; ch < NC; ch++) {
        int pf = ch + 1;
        if (pf < NC) { load_chunk(pf & 1, pf); CP_COMMIT; CP_WAIT1; }
        else         { CP_WAIT0; }
        __syncthreads();

        const __half* As = smh + (ch & 1) * GSTAGE_H;
        const __half* Bs = As + 128 * GSTRH;
#pragma unroll
        for (int ks = 0; ks < 4; ks++) {
            const int kk = ks * 16;
            uint32_t a[4][4], b[2][4];
#pragma unroll
            for (int mt = 0; mt < 4; mt++)
                ldsm4(a[mt], smem_addr(As + (wm * 64 + mt * 16 + lrA) * GSTRH + kk + lcA));
#pragma unroll
            for (int nt2 = 0; nt2 < 2; nt2++)
                ldsm4(b[nt2], smem_addr(Bs + (wn * 32 + nt2 * 16 + lrB4) * GSTRH + kk + lcB4));
#pragma unroll
            for (int mt = 0; mt < 4; mt++)
#pragma unroll
                for (int nt2 = 0; nt2 < 2; nt2++) {
                    mma16(c[mt][nt2 * 2 + 0], a[mt], b[nt2] + 0);
                    mma16(c[mt][nt2 * 2 + 1], a[mt], b[nt2] + 2);
                }
        }
        __syncthreads();   // all reads of this stage done before it is refilled
    }

    // epilogue (+ optional fused RoPE on fp32 accumulators)
#pragma unroll
    for (int mt = 0; mt < 4; mt++) {
        int row = m0 + wm * 64 + mt * 16 + g;
#pragma unroll
        for (int nt = 0; nt < 4; nt++) {
            int col = n0 + wn * 32 + nt * 8 + 2 * tg;
            float v0 = c[mt][nt][0], v1 = c[mt][nt][1];
            float v2 = c[mt][nt][2], v3 = c[mt][nt][3];
            if (rope) {
                int p = (col & 127) >> 1;
                int s0 = row & (SEQ - 1);
                int s1 = (row + 8) & (SEQ - 1);
                float c0 = fc[s0 * 64 + p], n0v = fs[s0 * 64 + p];
                float c1 = fc[s1 * 64 + p], n1v = fs[s1 * 64 + p];
                float t0 = v0 * c0 - v1 * n0v, t1 = v0 * n0v + v1 * c0;
                float t2 = v2 * c1 - v3 * n1v, t3 = v2 * n1v + v3 * c1;
                v0 = t0; v1 = t1; v2 = t2; v3 = t3;
            }
            if constexpr (sizeof(CT) == 2) {
                *(__half2*)&C[(size_t)row * N + col] = __floats2half2_rn(v0, v1);
                *(__half2*)&C[(size_t)(row + 8) * N + col] = __floats2half2_rn(v2, v3);
            } else {
                *(float2*)&C[(size_t)row * N + col] = make_float2(v0, v1);
                *(float2*)&C[(size_t)(row + 8) * N + col] = make_float2(v2, v3);
            }
        }
    }
}

// ================= flash attention (causal), fp16 mma.sync =================
// BM=128 q, BN=128 kv. 8 warps, each owns 16 q rows x full 128 kv. P in regs.
// K and V in natural [seq][hd] layout (V B-frags via ldmatrix.trans).
// K/V tiles double-buffered (170KB smem); Q loaded once. One batch per launch.
#define QSTRH 136                       // 128 + 8 pad
#define FQ_H (128*QSTRH)
#define FKV_H (128*QSTRH)
#define FLASH_SMEM ((FQ_H + 4*FKV_H) * 2)   // 174080 B

__global__ __launch_bounds__(256, 1)
void flash_f16(const __half* __restrict__ Q, const __half* __restrict__ K,
               const __half* __restrict__ V, __half* __restrict__ O, int b)
{
    extern __shared__ __half smh[];
    __half* Qs = smh;
    __half* Ks = Qs + FQ_H;              // 2 buffers
    __half* Vs = Ks + 2 * FKV_H;         // 2 buffers

    const int tid = threadIdx.x, wid = tid >> 5, lane = tid & 31;
    const int g = lane >> 2, tg = lane & 3;
    const int qt = (int)(gridDim.x - 1) - (int)blockIdx.x;   // heavy tiles first
    const int h = blockIdx.y;
    const int row0 = b * SEQ + qt * 128;
    const float scale = 0.08838834764831845f;
    const int lrA = lane & 15, lcA = (lane >> 4) << 3;
    const int lrB4 = (lane & 7) | ((lane >> 4) << 3);
    const int lcB4 = ((lane >> 3) & 1) << 3;
    const int lrV = (lane & 7) | ((lane >> 3) & 1) << 3;
    const int lcV = (lane >> 4) << 3;

    auto issue_tile = [&](int jt) {
        const int kv0 = jt << 7;
        __half* Kb = Ks + (jt & 1) * FKV_H;
        __half* Vb = Vs + (jt & 1) * FKV_H;
#pragma unroll
        for (int i = 0; i < 8; i++) {           // K: 128 rows x 16 granules
            int idx = tid + i * 256;
            int row = idx >> 4, gc = (idx & 15) << 3;
            cpasync16(smem_addr(Kb + row * QSTRH + gc),
                      K + (size_t)(b * SEQ + kv0 + row) * DM + h * HD + gc);
        }
#pragma unroll
        for (int i = 0; i < 8; i++) {           // V: same natural layout
            int idx = tid + i * 256;
            int row = idx >> 4, gc = (idx & 15) << 3;
            cpasync16(smem_addr(Vb + row * QSTRH + gc),
                      V + (size_t)(b * SEQ + kv0 + row) * DM + h * HD + gc);
        }
    };

    // Q tile: 128 rows x 16 granules = 2048
#pragma unroll
    for (int i = 0; i < 8; i++) {
        int idx = tid + i * 256;
        int row = idx >> 4, gc = (idx & 15) << 3;
        cpasync16(smem_addr(Qs + row * QSTRH + gc),
                  Q + (size_t)(row0 + row) * DM + h * HD + gc);
    }
    CP_COMMIT;
    issue_tile(0);
    CP_COMMIT;

    float o[16][4];
#pragma unroll
    for (int nt = 0; nt < 16; nt++)
#pragma unroll
        for (int j = 0; j < 4; j++) o[nt][j] = 0.f;
    float mrun0 = -INFINITY, mrun1 = -INFINITY, l0 = 0.f, l1 = 0.f;

    const int ntiles = qt + 1;
    const int qr0 = qt * 128 + wid * 16 + g;
    const int qr1 = qr0 + 8;

    for (int jt = 0; jt < ntiles; jt++) {
        const int kv0 = jt << 7;
        __syncthreads();                       // all warps done with buffer being refilled
        bool pf = (jt + 1 < ntiles);
        if (pf) issue_tile(jt + 1);
        CP_COMMIT;
        if (pf) { CP_WAIT1; } else { CP_WAIT0; }
        __syncthreads();

        const __half* Kb = Ks + (jt & 1) * FKV_H;
        const __half* Vb = Vs + (jt & 1) * FKV_H;

        // ---- S = Q @ K^T : this warp's 16 q rows x 128 kv
        float sc[16][4];
#pragma unroll
        for (int nt = 0; nt < 16; nt++)
#pragma unroll
            for (int j = 0; j < 4; j++) sc[nt][j] = 0.f;

#pragma unroll
        for (int ks = 0; ks < 8; ks++) {
            const int kk = ks * 16;
            uint32_t a[4];
            ldsm4(a, smem_addr(Qs + (wid * 16 + lrA) * QSTRH + kk + lcA));
#pragma unroll
            for (int nt2 = 0; nt2 < 8; nt2++) {
                uint32_t bf[4];
                ldsm4(bf, smem_addr(Kb + (nt2 * 16 + lrB4) * QSTRH + kk + lcB4));
                mma16(sc[nt2 * 2 + 0], a, bf + 0);
                mma16(sc[nt2 * 2 + 1], a, bf + 2);
            }
        }

        // ---- scale + causal mask (only the diagonal tile needs masking)
        const bool need_mask = (jt == qt);
#pragma unroll
        for (int nt = 0; nt < 16; nt++) {
            int kc = kv0 + nt * 8 + 2 * tg;
#pragma unroll
            for (int j = 0; j < 4; j++) {
                float s = sc[nt][j] * scale;
                if (need_mask) {
                    int qr = (j >= 2) ? qr1 : qr0;
                    if (kc + (j & 1) > qr) s = -1e30f;
                }
                sc[nt][j] = s;
            }
        }

        // ---- in-warp online softmax (rows g and g+8 of this warp's block)
        float mx0 = -INFINITY, mx1 = -INFINITY;
#pragma unroll
        for (int nt = 0; nt < 16; nt++) {
            mx0 = fmaxf(mx0, fmaxf(sc[nt][0], sc[nt][1]));
            mx1 = fmaxf(mx1, fmaxf(sc[nt][2], sc[nt][3]));
        }
        mx0 = fmaxf(mx0, __shfl_xor_sync(0xffffffffu, mx0, 1));
        mx0 = fmaxf(mx0, __shfl_xor_sync(0xffffffffu, mx0, 2));
        mx1 = fmaxf(mx1, __shfl_xor_sync(0xffffffffu, mx1, 1));
        mx1 = fmaxf(mx1, __shfl_xor_sync(0xffffffffu, mx1, 2));
        float mn0 = fmaxf(mrun0, mx0), mn1 = fmaxf(mrun1, mx1);
        float fac0 = __expf(mrun0 - mn0), fac1 = __expf(mrun1 - mn1);
        mrun0 = mn0; mrun1 = mn1;

        float s0 = 0.f, s1 = 0.f;
#pragma unroll
        for (int nt = 0; nt < 16; nt++) {
            sc[nt][0] = __expf(sc[nt][0] - mn0);
            sc[nt][1] = __expf(sc[nt][1] - mn0);
            sc[nt][2] = __expf(sc[nt][2] - mn1);
            sc[nt][3] = __expf(sc[nt][3] - mn1);
            s0 += sc[nt][0] + sc[nt][1];
            s1 += sc[nt][2] + sc[nt][3];
        }
        s0 += __shfl_xor_sync(0xffffffffu, s0, 1);
        s0 += __shfl_xor_sync(0xffffffffu, s0, 2);
        s1 += __shfl_xor_sync(0xffffffffu, s1, 1);
        s1 += __shfl_xor_sync(0xffffffffu, s1, 2);
        l0 = l0 * fac0 + s0;
        l1 = l1 * fac1 + s1;

#pragma unroll
        for (int nt = 0; nt < 16; nt++) {
            o[nt][0] *= fac0; o[nt][1] *= fac0;
            o[nt][2] *= fac1; o[nt][3] *= fac1;
        }

        // ---- O += P @ V ; P packed from sc regs; V B-frags via ldmatrix.trans
#pragma unroll
        for (int kb = 0; kb < 8; kb++) {
            uint32_t a[4];
            a[0] = packh2(sc[2 * kb][0],     sc[2 * kb][1]);
            a[1] = packh2(sc[2 * kb][2],     sc[2 * kb][3]);
            a[2] = packh2(sc[2 * kb + 1][0], sc[2 * kb + 1][1]);
            a[3] = packh2(sc[2 * kb + 1][2], sc[2 * kb + 1][3]);
            const int kk = kb * 16;
#pragma unroll
            for (int nt2 = 0; nt2 < 8; nt2++) {
                uint32_t bf[4];
                ldsm4t(bf, smem_addr(Vb + (kk + lrV) * QSTRH + nt2 * 16 + lcV));
                mma16(o[nt2 * 2 + 0], a, bf + 0);
                mma16(o[nt2 * 2 + 1], a, bf + 2);
            }
        }
    }

    // ---- epilogue
    float inv0 = 1.0f / l0, inv1 = 1.0f / l1;
    int row = row0 + wid * 16 + g;
#pragma unroll
    for (int nt = 0; nt < 16; nt++) {
        int col = h * HD + nt * 8 + 2 * tg;
        *(__half2*)&O[(size_t)row * DM + col] =
            __floats2half2_rn(o[nt][0] * inv0, o[nt][1] * inv0);
        *(__half2*)&O[(size_t)(row + 8) * DM + col] =
            __floats2half2_rn(o[nt][2] * inv1, o[nt][3] * inv1);
    }
}

// ---------------- small kernels ----------------
// src float: transpose [r,c] -> dst half [c,r]
__global__ __launch_bounds__(256) void trans_cvt(const float* __restrict__ src,
                                                 __half* __restrict__ dst, int R, int C)
{
    __shared__ float t[32][33];
    int c0 = blockIdx.x * 32, r0 = blockIdx.y * 32;
    int tx = threadIdx.x & 31, ty = threadIdx.x >> 5;
#pragma unroll
    for (int i = 0; i < 4; i++)
        t[ty + i * 8][tx] = src[(size_t)(r0 + ty + i * 8) * C + c0 + tx];
    __syncthreads();
#pragma unroll
    for (int i = 0; i < 4; i++)
        dst[(size_t)(c0 + ty + i * 8) * R + r0 + tx] = __float2half_rn(t[tx][ty + i * 8]);
}

__global__ __launch_bounds__(256) void rmsnorm_kernel(__half* __restrict__ x,
                                                      const float* __restrict__ w)
{
    const int row = blockIdx.x;
    __half* p = x + (size_t)row * LORA;
    const int t = threadIdx.x;
    float v0 = __half2float(p[t]), v1 = __half2float(p[t + 256]);
    float ss = v0 * v0 + v1 * v1;
#pragma unroll
    for (int o = 16; o; o >>= 1) ss += __shfl_xor_sync(0xffffffffu, ss, o);
    __shared__ float sred[8];
    if ((t & 31) == 0) sred[t >> 5] = ss;
    __syncthreads();
    float tot = 0.f;
#pragma unroll
    for (int i = 0; i < 8; i++) tot += sred[i];
    float inv = rsqrtf(tot * (1.0f / (float)LORA) + 1e-6f);
    p[t]       = __float2half_rn(v0 * inv * w[t]);
    p[t + 256] = __float2half_rn(v1 * inv * w[t + 256]);
}

// ---------------- launch ----------------
extern "C" void kernel_launch(void* const* d_in, const int* in_sizes, int n_in,
                              void* d_out, int out_size)
{
    const float* x     = (const float*)d_in[0];
    const float* fcos  = (const float*)d_in[1];
    const float* fsin  = (const float*)d_in[2];
    const float* w_kvc = (const float*)d_in[3];
    const float* kvw   = (const float*)d_in[4];
    const float* w_k   = (const float*)d_in[5];
    const float* w_v   = (const float*)d_in[6];
    const float* w_q   = (const float*)d_in[7];
    const float* w_o   = (const float*)d_in[8];
    float* out = (float*)d_out;

    __half *kvl, *Kb, *Vb, *Qb, *Ab;
    __half *wkvcT, *wkT, *wvT, *wqT, *woT;
    cudaGetSymbolAddress((void**)&kvl, g_kvlat);
    cudaGetSymbolAddress((void**)&Kb, g_k);
    cudaGetSymbolAddress((void**)&Vb, g_v);
    cudaGetSymbolAddress((void**)&Qb, g_q);
    cudaGetSymbolAddress((void**)&Ab, g_attn);
    cudaGetSymbolAddress((void**)&wkvcT, g_wkvcT);
    cudaGetSymbolAddress((void**)&wkT, g_wkT);
    cudaGetSymbolAddress((void**)&wvT, g_wvT);
    cudaGetSymbolAddress((void**)&wqT, g_wqT);
    cudaGetSymbolAddress((void**)&woT, g_woT);

    cudaFuncSetAttribute((void*)gemm_f16<__half, float>,  cudaFuncAttributeMaxDynamicSharedMemorySize, GEMM_SMEM);
    cudaFuncSetAttribute((void*)gemm_f16<__half, __half>, cudaFuncAttributeMaxDynamicSharedMemorySize, GEMM_SMEM);
    cudaFuncSetAttribute((void*)gemm_f16<float, __half>,  cudaFuncAttributeMaxDynamicSharedMemorySize, GEMM_SMEM);
    cudaFuncSetAttribute((void*)flash_f16, cudaFuncAttributeMaxDynamicSharedMemorySize, FLASH_SMEM);

    // one-time side streams + events (host resources; identical GPU work every call)
    static cudaStream_t s2 = nullptr, s3 = nullptr;
    static cudaEvent_t ev_root = nullptr, ev_wkvc = nullptr, ev_w = nullptr,
                       ev_q = nullptr, ev_f0 = nullptr, ev_out0 = nullptr;
    if (s2 == nullptr) {
        cudaStreamCreateWithFlags(&s2, cudaStreamNonBlocking);
        cudaStreamCreateWithFlags(&s3, cudaStreamNonBlocking);
        cudaEventCreateWithFlags(&ev_root, cudaEventDisableTiming);
        cudaEventCreateWithFlags(&ev_wkvc, cudaEventDisableTiming);
        cudaEventCreateWithFlags(&ev_w, cudaEventDisableTiming);
        cudaEventCreateWithFlags(&ev_q, cudaEventDisableTiming);
        cudaEventCreateWithFlags(&ev_f0, cudaEventDisableTiming);
        cudaEventCreateWithFlags(&ev_out0, cudaEventDisableTiming);
    }

    // ---- fork: root event on the capturing (main) stream FIRST ----
    cudaEventRecord(ev_root, 0);
    cudaStreamWaitEvent(s2, ev_root, 0);
    cudaStreamWaitEvent(s3, ev_root, 0);

    // ---- s2: non-q weight transposes (kv-critical ones first) ----
    trans_cvt<<<dim3(LORA / 32, DM / 32), 256, 0, s2>>>(w_kvc, wkvcT, DM, LORA);
    cudaEventRecord(ev_wkvc, s2);
    trans_cvt<<<dim3(DM / 32, LORA / 32), 256, 0, s2>>>(w_k, wkT, LORA, DM);
    trans_cvt<<<dim3(DM / 32, LORA / 32), 256, 0, s2>>>(w_v, wvT, LORA, DM);
    cudaEventRecord(ev_w, s2);
    // wo transpose trails on s2 (only needed by the s2 out-GEMM, which is in-order)
    trans_cvt<<<dim3(DM / 32, DM / 32), 256, 0, s2>>>(w_o, woT, DM, DM);

    // ---- s3: q branch (A = x fp32, converted in-kernel) ----
    trans_cvt<<<dim3(DM / 32, DM / 32), 256, 0, s3>>>(w_q, wqT, DM, DM);
    gemm_f16<__half, float><<<dim3(DM / 128, ROWS / 128), 256, GEMM_SMEM, s3>>>(
        x, wqT, Qb, ROWS, DM, DM, fcos, fsin, nullptr, nullptr, 0);
    cudaEventRecord(ev_q, s3);

    // ---- main: kv chain (A = x fp32, converted in-kernel) ----
    cudaStreamWaitEvent(0, ev_wkvc, 0);
    gemm_f16<__half, float><<<dim3(LORA / 128, ROWS / 128), 256, GEMM_SMEM>>>(
        x, wkvcT, kvl, ROWS, LORA, DM, nullptr, nullptr, nullptr, nullptr, 0);
    rmsnorm_kernel<<<ROWS, 256>>>(kvl, kvw);
    cudaStreamWaitEvent(0, ev_w, 0);
    // merged k-up (rope) + v-up (no rope): one 1024-CTA launch
    gemm_f16<__half, __half><<<dim3(2 * (DM / 128), ROWS / 128), 256, GEMM_SMEM>>>(
        kvl, wkT, Kb, ROWS, DM, LORA, fcos, fsin, wvT, Vb, DM / 128);

    // ---- join q branch, then flash (batch-split) with out-GEMM overlap ----
    cudaStreamWaitEvent(0, ev_q, 0);
    // flash batch 0
    flash_f16<<<dim3(SEQ / 128, NH, 1), 256, FLASH_SMEM>>>(Qb, Kb, Vb, Ab, 0);
    cudaEventRecord(ev_f0, 0);
    // flash batch 1 (main) overlaps out-GEMM of batch-0 rows (s2; woT ready in s2 order)
    flash_f16<<<dim3(SEQ / 128, NH, 1), 256, FLASH_SMEM>>>(Qb, Kb, Vb, Ab, 1);
    cudaStreamWaitEvent(s2, ev_f0, 0);
    gemm_f16<float, __half><<<dim3(DM / 128, SEQ / 128), 256, GEMM_SMEM, s2>>>(
        Ab, woT, out, SEQ, DM, DM, nullptr, nullptr, nullptr, nullptr, 0);
    cudaEventRecord(ev_out0, s2);
    // out-GEMM for batch-1 rows on main
    gemm_f16<float, __half><<<dim3(DM / 128, SEQ / 128), 256, GEMM_SMEM>>>(
        Ab + (size_t)SEQ * DM, woT, out + (size_t)SEQ * DM, SEQ, DM, DM,
        nullptr, nullptr, nullptr, nullptr, 0);
    // join side streams back into main before capture ends
    cudaStreamWaitEvent(0, ev_out0, 0);
}